// round 1
// baseline (speedup 1.0000x reference)
#include <cuda_runtime.h>

// 5-level db4 DWT, symmetric extension (pywt 'symmetric'), per-row cascade.
// x: (64,64,4096) fp32 -> out = concat(approx[134], d5[134], d4[262],
//                                      d3[518], d2[1029], d1[2051]) per row.

#define NROWS   4096
#define NTHREADS 256

// Level lengths
#define L0 4096
#define L1 2051
#define L2 1029
#define L3 518
#define L4 262
#define L5 134

// Output-segment base offsets (elements), order: approx, d5, d4, d3, d2, d1
#define O_APPROX 0
#define O_D5 (NROWS * L5)                       // 548864
#define O_D4 (O_D5 + NROWS * L5)                // 1097728
#define O_D3 (O_D4 + NROWS * L4)                // 2170880
#define O_D2 (O_D3 + NROWS * L3)                // 4292608
#define O_D1 (O_D2 + NROWS * L2)                // 8507392

__device__ __forceinline__ float symext(const float* __restrict__ a, int i, int L) {
    // ext index i in [0, L+13); ext = symmetric-pad-7 both sides, first dropped.
    int k = i - 6;
    k = (k < 0) ? (-1 - k) : k;
    k = (k >= L) ? (2 * L - 1 - k) : k;
    return a[k];
}

// One DWT level: in[L] (smem) -> cA[M] (smem or gmem), cD[M] (gmem).
// y[j] = sum_s filt[s] * ext[2j + 7 - s]
__device__ __forceinline__ void dwt_level(const float* __restrict__ in, int L,
                                          float* __restrict__ cA,
                                          float* __restrict__ cD,
                                          int M, int tid) {
    const float LOF[8] = {-0.010597401784997278f,  0.032883011666982945f,
                           0.030841381835986965f, -0.18703481171888114f,
                          -0.02798376941698385f,   0.6308807679295904f,
                           0.7148465705525415f,    0.23037781330885523f};
    const float HIF[8] = {-0.23037781330885523f,   0.7148465705525415f,
                          -0.6308807679295904f,   -0.02798376941698385f,
                           0.18703481171888114f,   0.030841381835986965f,
                          -0.032883011666982945f, -0.010597401784997278f};
    for (int j = tid; j < M; j += NTHREADS) {
        const int base = 2 * j + 7;
        float lo = 0.f, hi = 0.f;
#pragma unroll
        for (int s = 0; s < 8; s++) {
            float v = symext(in, base - s, L);
            lo = fmaf(LOF[s], v, lo);
            hi = fmaf(HIF[s], v, hi);
        }
        cA[j] = lo;
        cD[j] = hi;
    }
}

__global__ __launch_bounds__(NTHREADS, 1)
void wavelet5_kernel(const float* __restrict__ x, float* __restrict__ out) {
    __shared__ float bufA[L0];
    __shared__ float bufB[L1 + 1];

    const int row = blockIdx.x;
    const int tid = threadIdx.x;

    // Coalesced float4 load of the row into smem
    const float4* src = reinterpret_cast<const float4*>(x + (size_t)row * L0);
    float4* dstA = reinterpret_cast<float4*>(bufA);
#pragma unroll
    for (int i = tid; i < L0 / 4; i += NTHREADS) dstA[i] = src[i];
    __syncthreads();

    // Level 1: bufA(4096) -> cA bufB(2051), cD -> d1
    dwt_level(bufA, L0, bufB, out + O_D1 + (size_t)row * L1, L1, tid);
    __syncthreads();
    // Level 2: bufB(2051) -> cA bufA(1029), cD -> d2
    dwt_level(bufB, L1, bufA, out + O_D2 + (size_t)row * L2, L2, tid);
    __syncthreads();
    // Level 3: bufA(1029) -> cA bufB(518), cD -> d3
    dwt_level(bufA, L2, bufB, out + O_D3 + (size_t)row * L3, L3, tid);
    __syncthreads();
    // Level 4: bufB(518) -> cA bufA(262), cD -> d4
    dwt_level(bufB, L3, bufA, out + O_D4 + (size_t)row * L4, L4, tid);
    __syncthreads();
    // Level 5: bufA(262) -> cA -> approx (gmem), cD -> d5
    dwt_level(bufA, L4, out + O_APPROX + (size_t)row * L5,
              out + O_D5 + (size_t)row * L5, L5, tid);
}

extern "C" void kernel_launch(void* const* d_in, const int* in_sizes, int n_in,
                              void* d_out, int out_size) {
    const float* x = (const float*)d_in[0];
    float* out = (float*)d_out;
    (void)in_sizes; (void)n_in; (void)out_size;
    wavelet5_kernel<<<NROWS, NTHREADS>>>(x, out);
}

// round 2
// speedup vs baseline: 1.2713x; 1.2713x over previous
#include <cuda_runtime.h>

// 5-level db4 DWT, symmetric extension, per-row cascade with pre-padded
// smem buffers (no reflect logic in inner loop) and float4 LDS pair-blocking.

#define NROWS    4096
#define NT       256

// Level input lengths
#define L0 4096
#define L1 2051
#define L2 1029
#define L3 518
#define L4 262
#define L5 134

// Output-segment base offsets (elements): approx, d5, d4, d3, d2, d1
#define O_APPROX 0
#define O_D5 (NROWS * L5)
#define O_D4 (O_D5 + NROWS * L5)
#define O_D3 (O_D4 + NROWS * L4)
#define O_D2 (O_D3 + NROWS * L3)
#define O_D1 (O_D2 + NROWS * L2)

// Filters in p-order: y[j] = sum_r RF[r] * p[2j + r], p = padded extension.
// RLO[r] = DEC_LO[7-r], RHI[r] = DEC_HI[7-r].
#define RLO0  0.23037781330885523f
#define RLO1  0.7148465705525415f
#define RLO2  0.6308807679295904f
#define RLO3 -0.02798376941698385f
#define RLO4 -0.18703481171888114f
#define RLO5  0.030841381835986965f
#define RLO6  0.032883011666982945f
#define RLO7 -0.010597401784997278f

#define RHI0 -0.010597401784997278f
#define RHI1 -0.032883011666982945f
#define RHI2  0.030841381835986965f
#define RHI3  0.18703481171888114f
#define RHI4 -0.02798376941698385f
#define RHI5 -0.6308807679295904f
#define RHI6  0.7148465705525415f
#define RHI7 -0.23037781330885523f

// One level over a padded buffer p (p[i] = extended signal, i in [0, M_in+13]).
// Computes M outputs. cD always to gmem. cA either to gmem (LAST) or into the
// next padded smem buffer (interior at +6, boundary mirrors written inline).
template<bool LAST>
__device__ __forceinline__ void dwt_level(const float* __restrict__ p, int M,
                                          float* __restrict__ cA,
                                          float* __restrict__ cD,
                                          int tid) {
    const float4* __restrict__ p4 = reinterpret_cast<const float4*>(p);
    const int NP = (M + 1) >> 1;
    for (int pi = tid; pi < NP; pi += NT) {
        float4 a = p4[pi];
        float4 b = p4[pi + 1];
        float4 c = p4[pi + 2];
        // w[0..11] = p[4pi .. 4pi+11]
        // output j0 = 2pi uses w[0..7]; j1 = 2pi+1 uses w[2..9]
        float lo0, hi0, lo1, hi1;
        lo0 = RLO0 * a.x;          hi0 = RHI0 * a.x;
        lo1 = RLO0 * a.z;          hi1 = RHI0 * a.z;
        lo0 = fmaf(RLO1, a.y, lo0); hi0 = fmaf(RHI1, a.y, hi0);
        lo1 = fmaf(RLO1, a.w, lo1); hi1 = fmaf(RHI1, a.w, hi1);
        lo0 = fmaf(RLO2, a.z, lo0); hi0 = fmaf(RHI2, a.z, hi0);
        lo1 = fmaf(RLO2, b.x, lo1); hi1 = fmaf(RHI2, b.x, hi1);
        lo0 = fmaf(RLO3, a.w, lo0); hi0 = fmaf(RHI3, a.w, hi0);
        lo1 = fmaf(RLO3, b.y, lo1); hi1 = fmaf(RHI3, b.y, hi1);
        lo0 = fmaf(RLO4, b.x, lo0); hi0 = fmaf(RHI4, b.x, hi0);
        lo1 = fmaf(RLO4, b.z, lo1); hi1 = fmaf(RHI4, b.z, hi1);
        lo0 = fmaf(RLO5, b.y, lo0); hi0 = fmaf(RHI5, b.y, hi0);
        lo1 = fmaf(RLO5, b.w, lo1); hi1 = fmaf(RHI5, b.w, hi1);
        lo0 = fmaf(RLO6, b.z, lo0); hi0 = fmaf(RHI6, b.z, hi0);
        lo1 = fmaf(RLO6, c.x, lo1); hi1 = fmaf(RHI6, c.x, hi1);
        lo0 = fmaf(RLO7, b.w, lo0); hi0 = fmaf(RHI7, b.w, hi0);
        lo1 = fmaf(RLO7, c.y, lo1); hi1 = fmaf(RHI7, c.y, hi1);

        const int j0 = 2 * pi;
        const int j1 = j0 + 1;
        cD[j0] = hi0;
        if (LAST) {
            cA[j0] = lo0;
        } else {
            cA[6 + j0] = lo0;
            if (j0 <= 5)      cA[5 - j0] = lo0;           // left mirror pad
            if (j0 >= M - 8)  cA[2 * M + 5 - j0] = lo0;   // right mirror pad
        }
        if (j1 < M) {
            cD[j1] = hi1;
            if (LAST) {
                cA[j1] = lo1;
            } else {
                cA[6 + j1] = lo1;
                if (j1 <= 5)      cA[5 - j1] = lo1;
                if (j1 >= M - 8)  cA[2 * M + 5 - j1] = lo1;
            }
        }
    }
}

__global__ __launch_bounds__(NT, 1)
void wavelet5_kernel(const float* __restrict__ x, float* __restrict__ out) {
    // Padded buffers: [pad6 | signal | pad8 | slack]. Slack covers the
    // harmless over-read of the discarded tail output when M is odd.
    __shared__ __align__(16) float bufA[L0 + 20];
    __shared__ __align__(16) float bufB[L1 + 20];

    const int row = blockIdx.x;
    const int tid = threadIdx.x;
    const float* __restrict__ xr = x + (size_t)row * L0;

    // Fill bufA = padded extension of the input row.
    {
        const float2* __restrict__ x2 = reinterpret_cast<const float2*>(xr);
        float2* __restrict__ p2 = reinterpret_cast<float2*>(bufA + 6);
#pragma unroll 4
        for (int i = tid; i < L0 / 2; i += NT) p2[i] = x2[i];
        if (tid < 6) {
            bufA[tid] = xr[5 - tid];                      // left pad
        } else if (tid < 14) {
            const int i = L0 + tid;                       // i in [L0+6, L0+13]
            bufA[i] = xr[2 * L0 + 5 - i];                 // right pad
        }
    }
    __syncthreads();

    float* __restrict__ d1 = out + O_D1 + (size_t)row * L1;
    float* __restrict__ d2 = out + O_D2 + (size_t)row * L2;
    float* __restrict__ d3 = out + O_D3 + (size_t)row * L3;
    float* __restrict__ d4 = out + O_D4 + (size_t)row * L4;
    float* __restrict__ d5 = out + O_D5 + (size_t)row * L5;
    float* __restrict__ ap = out + O_APPROX + (size_t)row * L5;

    dwt_level<false>(bufA, L1, bufB, d1, tid);  // 4096 -> 2051
    __syncthreads();
    dwt_level<false>(bufB, L2, bufA, d2, tid);  // 2051 -> 1029
    __syncthreads();
    dwt_level<false>(bufA, L3, bufB, d3, tid);  // 1029 -> 518
    __syncthreads();
    dwt_level<false>(bufB, L4, bufA, d4, tid);  // 518  -> 262
    __syncthreads();
    dwt_level<true>(bufA, L5, ap, d5, tid);     // 262  -> 134
}

extern "C" void kernel_launch(void* const* d_in, const int* in_sizes, int n_in,
                              void* d_out, int out_size) {
    const float* x = (const float*)d_in[0];
    float* out = (float*)d_out;
    (void)in_sizes; (void)n_in; (void)out_size;
    wavelet5_kernel<<<NROWS, NT>>>(x, out);
}